// round 11
// baseline (speedup 1.0000x reference)
#include <cuda_runtime.h>
#include <math.h>

// YOLO loss — single fused launch. TMA (cp.async.bulk) double-buffered
// block tiles: pred/tcls/tbox staged contiguously to smem by the bulk-copy
// engine, mbarrier completion, 1 block/SM. Outputs 5 f32.

#define S_GRID_INV (1.0f / 14.0f)
#define L_COORD 5.0f
#define L_NOOBJ 0.5f
#define TPB 256
#define NWARP (TPB / 32)
#define CPB 512                    // cells per block-tile
#define PRED_B (CPB * 120)         // 61440 B
#define TCLS_B (CPB * 80)          // 40960 B
#define TBOX_B (CPB * 16)          // 8192 B
#define BUF_B  (PRED_B + TCLS_B + TBOX_B)   // 110592 B
#define HDR_B  512                 // red scratch + mbarriers
#define SMEM_BYTES (HDR_B + 2 * BUF_B)      // 221696 B

__device__ double g_acc[4];      // cls, noobj(raw), reg(raw), containing
__device__ unsigned g_counter;   // zero-init; reset by last block each run

extern __shared__ __align__(16) char dsm[];

__device__ __forceinline__ unsigned smem_u32(const void* p) {
    return (unsigned)__cvta_generic_to_shared(p);
}

__device__ __forceinline__ void mbar_init(unsigned mbar, unsigned count) {
    asm volatile("mbarrier.init.shared.b64 [%0], %1;"
                 :: "r"(mbar), "r"(count) : "memory");
}

__device__ __forceinline__ void mbar_expect_tx(unsigned mbar, unsigned bytes) {
    asm volatile("mbarrier.arrive.expect_tx.shared.b64 _, [%0], %1;"
                 :: "r"(mbar), "r"(bytes) : "memory");
}

__device__ __forceinline__ void mbar_wait(unsigned mbar, unsigned parity) {
    asm volatile(
        "{\n\t"
        ".reg .pred P;\n"
        "WAIT_%=:\n\t"
        "mbarrier.try_wait.parity.acquire.cta.shared::cta.b64 P, [%0], %1, 0x989680;\n\t"
        "@P bra DONE_%=;\n\t"
        "bra WAIT_%=;\n"
        "DONE_%=:\n\t"
        "}"
        :: "r"(mbar), "r"(parity) : "memory");
}

__device__ __forceinline__ void bulk_copy(unsigned sdst, const void* gsrc,
                                          unsigned bytes, unsigned mbar) {
    asm volatile(
        "cp.async.bulk.shared::cta.global.mbarrier::complete_tx::bytes "
        "[%0], [%1], %2, [%3];"
        :: "r"(sdst), "l"(gsrc), "r"(bytes), "r"(mbar) : "memory");
}

// compute one cell from smem tile buffers
__device__ __forceinline__ void computeCell(
    const char* buf, int r, bool m,
    float& s_cls, float& s_noobj, float& s_reg, float& s_cont)
{
    const float2* mp2 = (const float2*)(buf + r * 120);

    if (!m) {
        float cf0 = mp2[2].x;    // pred float idx 4
        float cf1 = mp2[4].y;    // pred float idx 9
        s_noobj += cf0 * cf0 + cf1 * cf1;
        return;
    }

    float pv[10];
#pragma unroll
    for (int j = 0; j < 5; j++) {
        float2 v = mp2[j];
        pv[2 * j]     = v.x;
        pv[2 * j + 1] = v.y;
    }

    // class loss
    {
        const float4* tc4 = (const float4*)(buf + PRED_B + r * 80);
        const float2* mc2 = (const float2*)(buf + r * 120 + 40);
        float cls = 0.f;
#pragma unroll
        for (int j = 0; j < 5; j++) {
            float4 t = tc4[j];
            float2 a = mc2[2 * j];
            float2 b = mc2[2 * j + 1];
            float d0 = t.x - a.x;
            float d1 = t.y - a.y;
            float d2 = t.z - b.x;
            float d3 = t.w - b.y;
            cls += d0 * d0 + d1 * d1 + d2 * d2 + d3 * d3;
        }
        s_cls += cls;
    }

    float4 tb = *(const float4*)(buf + PRED_B + TCLS_B + r * 16);
    float t_cx = tb.x * S_GRID_INV;
    float t_cy = tb.y * S_GRID_INV;
    float t_x1 = t_cx - 0.5f * tb.z;
    float t_y1 = t_cy - 0.5f * tb.w;
    float t_x2 = t_cx + 0.5f * tb.z;
    float t_y2 = t_cy + 0.5f * tb.w;
    float area_t = (t_x2 - t_x1) * (t_y2 - t_y1);

    float iou[2];
#pragma unroll
    for (int b = 0; b < 2; b++) {
        float px = pv[5 * b + 0] * S_GRID_INV;
        float py = pv[5 * b + 1] * S_GRID_INV;
        float pw = pv[5 * b + 2];
        float ph = pv[5 * b + 3];
        float p_x1 = px - 0.5f * pw;
        float p_y1 = py - 0.5f * ph;
        float p_x2 = px + 0.5f * pw;
        float p_y2 = py + 0.5f * ph;
        float lt_x = fmaxf(t_x1, p_x1);
        float lt_y = fmaxf(t_y1, p_y1);
        float rb_x = fminf(t_x2, p_x2);
        float rb_y = fminf(t_y2, p_y2);
        float w = fmaxf(rb_x - lt_x, 0.0f);
        float h = fmaxf(rb_y - lt_y, 0.0f);
        float inter = w * h;
        float area_p = (p_x2 - p_x1) * (p_y2 - p_y1);
        iou[b] = inter / (area_t + area_p - inter);
    }

    bool sel = iou[1] > iou[0];     // first max wins on tie
    float best_iou = sel ? iou[1] : iou[0];
    float bb_x = sel ? pv[5] : pv[0];
    float bb_y = sel ? pv[6] : pv[1];
    float bb_w = sel ? pv[7] : pv[2];
    float bb_h = sel ? pv[8] : pv[3];
    float bb_c = sel ? pv[9] : pv[4];

    float dx = bb_x - tb.x;
    float dy = bb_y - tb.y;
    float sw = sqrtf(bb_w) - sqrtf(tb.z);
    float sh = sqrtf(bb_h) - sqrtf(tb.w);
    s_reg += dx * dx + dy * dy + sw * sw + sh * sh;

    float dc = best_iou - bb_c;
    s_cont += dc * dc;
}

__global__ void __launch_bounds__(TPB, 1) yolo_fused_kernel(
    const float* __restrict__ pred,
    const float* __restrict__ tbox,
    const float* __restrict__ tcls,
    const void* __restrict__ maskv,
    int ncell, int n_batch, int ntiles, float* __restrict__ out)
{
    const int tid = threadIdx.x;
    const int warp = tid >> 5;
    const int lane = tid & 31;

    float* red = (float*)dsm;                        // 4*NWARP floats
    unsigned mbar[2];
    mbar[0] = smem_u32(dsm + 256);
    mbar[1] = smem_u32(dsm + 272);
    char* buf[2];
    buf[0] = dsm + HDR_B;
    buf[1] = dsm + HDR_B + BUF_B;

    // ---- mask dtype detection (first 32 words, warp-uniform) ----
    int mode;
    {
        unsigned w0 = ((const unsigned*)maskv)[lane];
        bool gt1 = w0 > 1u;
        bool bad = ((w0 & 0xFFu) > 1u) | (((w0 >> 8) & 0xFFu) > 1u) |
                   (((w0 >> 16) & 0xFFu) > 1u) | ((w0 >> 24) > 1u);
        unsigned bg = __ballot_sync(0xFFFFFFFFu, gt1);
        unsigned bb = __ballot_sync(0xFFFFFFFFu, bad);
        mode = (bg == 0) ? 0 : (bb ? 2 : 1);
    }

    if (tid == 0) {
        mbar_init(mbar[0], 1);
        mbar_init(mbar[1], 1);
    }
    __syncthreads();

    float s_cls = 0.f, s_noobj = 0.f, s_reg = 0.f, s_cont = 0.f;

    const int t0 = blockIdx.x;
    unsigned ph[2] = {0u, 0u};
    bool issued[2] = {false, false};

    // prologue: stage first tile into buf0
    if (t0 < ntiles) {
        bool full = ((long long)(t0 + 1)) * CPB <= (long long)ncell;
        if (full) {
            if (tid == 0) {
                unsigned s0 = smem_u32(buf[0]);
                mbar_expect_tx(mbar[0], BUF_B);
                bulk_copy(s0, (const char*)pred + (size_t)t0 * PRED_B,
                          PRED_B, mbar[0]);
                bulk_copy(s0 + PRED_B, (const char*)tcls + (size_t)t0 * TCLS_B,
                          TCLS_B, mbar[0]);
                bulk_copy(s0 + PRED_B + TCLS_B,
                          (const char*)tbox + (size_t)t0 * TBOX_B,
                          TBOX_B, mbar[0]);
            }
            issued[0] = true;
        }
    }

    int sel = 0;
    for (int t = t0; t < ntiles; t += gridDim.x, sel ^= 1) {
        const int cell0 = t * CPB;
        const int nx = sel ^ 1;

        // stage tile t+grid into the other buffer (free since last iter)
        int tn = t + (int)gridDim.x;
        if (tn < ntiles && ((long long)(tn + 1)) * CPB <= (long long)ncell) {
            if (tid == 0) {
                unsigned sx = smem_u32(buf[nx]);
                mbar_expect_tx(mbar[nx], BUF_B);
                bulk_copy(sx, (const char*)pred + (size_t)tn * PRED_B,
                          PRED_B, mbar[nx]);
                bulk_copy(sx + PRED_B,
                          (const char*)tcls + (size_t)tn * TCLS_B,
                          TCLS_B, mbar[nx]);
                bulk_copy(sx + PRED_B + TCLS_B,
                          (const char*)tbox + (size_t)tn * TBOX_B,
                          TBOX_B, mbar[nx]);
            }
            issued[nx] = true;
        } else {
            issued[nx] = false;
        }

        // masks for my two cells (LDG overlaps mbarrier wait)
        const int c0 = cell0 + tid;
        const int c1 = cell0 + TPB + tid;
        bool m0 = false, m1 = false;
        if (mode == 0) {
            const int* mi = (const int*)maskv;
            if (c0 < ncell) m0 = mi[c0] != 0;
            if (c1 < ncell) m1 = mi[c1] != 0;
        } else if (mode == 1) {
            const unsigned char* mb = (const unsigned char*)maskv;
            if (c0 < ncell) m0 = mb[c0] != 0;
            if (c1 < ncell) m1 = mb[c1] != 0;
        } else {
            const float* mf = (const float*)maskv;
            if (c0 < ncell) m0 = mf[c0] != 0.0f;
            if (c1 < ncell) m1 = mf[c1] != 0.0f;
        }

        if (issued[sel]) {
            mbar_wait(mbar[sel], ph[sel]);
            ph[sel] ^= 1u;
            const char* b = buf[sel];
            if (c0 < ncell) computeCell(b, tid, m0, s_cls, s_noobj, s_reg, s_cont);
            if (c1 < ncell) computeCell(b, TPB + tid, m1, s_cls, s_noobj, s_reg, s_cont);
        } else {
            // partial-tile fallback: direct global (rare / never for full grids)
#pragma unroll
            for (int half = 0; half < 2; half++) {
                int c = half ? c1 : c0;
                bool m = half ? m1 : m0;
                if (c >= ncell) continue;
                const float* p = pred + (size_t)c * 30;
                if (!m) {
                    float a = p[4], bq = p[9];
                    s_noobj += a * a + bq * bq;
                    continue;
                }
                float pv[10];
                for (int q = 0; q < 10; q++) pv[q] = p[q];
                float cls = 0.f;
                const float* tc = tcls + (size_t)c * 20;
                for (int j = 0; j < 20; j++) {
                    float d = tc[j] - p[10 + j];
                    cls += d * d;
                }
                s_cls += cls;
                float4 tb = ((const float4*)tbox)[c];
                float t_cx = tb.x * S_GRID_INV, t_cy = tb.y * S_GRID_INV;
                float t_x1 = t_cx - 0.5f * tb.z, t_y1 = t_cy - 0.5f * tb.w;
                float t_x2 = t_cx + 0.5f * tb.z, t_y2 = t_cy + 0.5f * tb.w;
                float area_t = (t_x2 - t_x1) * (t_y2 - t_y1);
                float iou[2];
                for (int b2 = 0; b2 < 2; b2++) {
                    float px = pv[5 * b2 + 0] * S_GRID_INV;
                    float py = pv[5 * b2 + 1] * S_GRID_INV;
                    float pw = pv[5 * b2 + 2], phh = pv[5 * b2 + 3];
                    float p_x1 = px - 0.5f * pw, p_y1 = py - 0.5f * phh;
                    float p_x2 = px + 0.5f * pw, p_y2 = py + 0.5f * phh;
                    float w = fmaxf(fminf(t_x2, p_x2) - fmaxf(t_x1, p_x1), 0.f);
                    float h = fmaxf(fminf(t_y2, p_y2) - fmaxf(t_y1, p_y1), 0.f);
                    float inter = w * h;
                    float area_p = (p_x2 - p_x1) * (p_y2 - p_y1);
                    iou[b2] = inter / (area_t + area_p - inter);
                }
                bool selx = iou[1] > iou[0];
                float best_iou = selx ? iou[1] : iou[0];
                float bb_x = selx ? pv[5] : pv[0];
                float bb_y = selx ? pv[6] : pv[1];
                float bb_w = selx ? pv[7] : pv[2];
                float bb_h = selx ? pv[8] : pv[3];
                float bb_c = selx ? pv[9] : pv[4];
                float dx = bb_x - tb.x, dy = bb_y - tb.y;
                float sw = sqrtf(bb_w) - sqrtf(tb.z);
                float sh = sqrtf(bb_h) - sqrtf(tb.w);
                s_reg += dx * dx + dy * dy + sw * sw + sh * sh;
                float dc = best_iou - bb_c;
                s_cont += dc * dc;
            }
        }
        __syncthreads();   // all threads done with buf[sel] before reissue
    }

    // ---- warp reduction, then block reduction ----
#pragma unroll
    for (int off = 16; off; off >>= 1) {
        s_cls   += __shfl_down_sync(0xFFFFFFFFu, s_cls,   off);
        s_noobj += __shfl_down_sync(0xFFFFFFFFu, s_noobj, off);
        s_reg   += __shfl_down_sync(0xFFFFFFFFu, s_reg,   off);
        s_cont  += __shfl_down_sync(0xFFFFFFFFu, s_cont,  off);
    }
    if (lane == 0) {
        red[0 * NWARP + warp] = s_cls;
        red[1 * NWARP + warp] = s_noobj;
        red[2 * NWARP + warp] = s_reg;
        red[3 * NWARP + warp] = s_cont;
    }
    __syncthreads();

    __shared__ bool s_last;
    if (tid == 0) {
        float a0 = 0.f, a1 = 0.f, a2 = 0.f, a3 = 0.f;
#pragma unroll
        for (int w = 0; w < NWARP; w++) {
            a0 += red[0 * NWARP + w];
            a1 += red[1 * NWARP + w];
            a2 += red[2 * NWARP + w];
            a3 += red[3 * NWARP + w];
        }
        atomicAdd(&g_acc[0], (double)a0);
        atomicAdd(&g_acc[1], (double)a1);
        atomicAdd(&g_acc[2], (double)a2);
        atomicAdd(&g_acc[3], (double)a3);

        __threadfence();
        unsigned old = atomicAdd(&g_counter, 1u);
        s_last = (old == gridDim.x - 1);
    }
    __syncthreads();

    if (s_last && tid == 0) {
        double cls   = atomicAdd(&g_acc[0], 0.0);
        double noobj = (double)L_NOOBJ * atomicAdd(&g_acc[1], 0.0);
        double reg   = (double)L_COORD * atomicAdd(&g_acc[2], 0.0);
        double cont  = atomicAdd(&g_acc[3], 0.0);
        double total = (cls + noobj + reg + cont) / (double)n_batch;
        out[0] = (float)total;
        out[1] = (float)reg;
        out[2] = (float)cont;
        out[3] = (float)noobj;
        out[4] = (float)cls;
        g_acc[0] = 0.0; g_acc[1] = 0.0; g_acc[2] = 0.0; g_acc[3] = 0.0;
        __threadfence();
        g_counter = 0u;
    }
}

extern "C" void kernel_launch(void* const* d_in, const int* in_sizes, int n_in,
                              void* d_out, int out_size) {
    // Identify inputs by element count: pred = 30n, tcls = 20n, tbox = 4n, mask = n
    const void* ptrs[4] = {d_in[0], d_in[1], d_in[2], d_in[3]};
    long long sz[4] = {in_sizes[0], in_sizes[1], in_sizes[2], in_sizes[3]};

    int im = 0;
    for (int i = 1; i < 4; i++) if (sz[i] < sz[im]) im = i;
    long long n = sz[im];

    const float* pred = nullptr;
    const float* tbox = nullptr;
    const float* tcls = nullptr;
    const void*  hmask = ptrs[im];
    for (int i = 0; i < 4; i++) {
        if (i == im) continue;
        if (sz[i] == 30 * n) pred = (const float*)ptrs[i];
        else if (sz[i] == 20 * n) tcls = (const float*)ptrs[i];
        else if (sz[i] == 4 * n) tbox = (const float*)ptrs[i];
    }

    int ncell = (int)n;                 // 802816
    int n_batch = ncell / (14 * 14);    // 4096
    int ntiles = (ncell + CPB - 1) / CPB;   // 1568

    cudaFuncSetAttribute(yolo_fused_kernel,
                         cudaFuncAttributeMaxDynamicSharedMemorySize,
                         SMEM_BYTES);
    int dev = 0;
    cudaGetDevice(&dev);
    int nsm = 148;
    cudaDeviceGetAttribute(&nsm, cudaDevAttrMultiProcessorCount, dev);

    int blocks = (ntiles < nsm) ? ntiles : nsm;   // 1 block per SM
    yolo_fused_kernel<<<blocks, TPB, SMEM_BYTES>>>(
        pred, tbox, tcls, hmask, ncell, n_batch, ntiles, (float*)d_out);
}

// round 12
// speedup vs baseline: 1.0535x; 1.0535x over previous
#include <cuda_runtime.h>
#include <math.h>

// YOLO loss — fused single launch. cp.async staging with sector-aware
// predication: pred 16B chunks are loaded only if they overlap a masked
// cell or contain a confidence slot. tcls/tbox streamed direct (masked
// only). Outputs 5 f32: total, reg, containing, noobj, cls.

#define S_GRID_INV (1.0f / 14.0f)
#define L_COORD 5.0f
#define L_NOOBJ 0.5f
#define TPB 128
#define NWARP (TPB / 32)
#define CPW 64                 // cells per warp
#define CPB (NWARP * CPW)      // 256 cells per block
#define PROW 30                // floats per pred row (unpadded)

__device__ double g_acc[4];      // cls, noobj(raw), reg(raw), containing
__device__ unsigned g_counter;   // zero-init; reset by last block each run

__global__ void __launch_bounds__(TPB, 7) yolo_fused_kernel(
    const float* __restrict__ pred,
    const float* __restrict__ tbox,
    const float* __restrict__ tcls,
    const void* __restrict__ maskv,
    int ncell, int n_batch, float* __restrict__ out)
{
    __shared__ float sp[NWARP * CPW * PROW];   // 30 KB
    __shared__ float sm[4][NWARP];
    __shared__ bool s_last;

    const int tid  = threadIdx.x;
    const int warp = tid >> 5;
    const int lane = tid & 31;
    const int cellBase = blockIdx.x * CPB + warp * CPW;

    float* wsp = sp + warp * (CPW * PROW);

    // ---- mask dtype detection: warp-local ballot over first 32 words ----
    int mode;
    {
        unsigned w0 = ((const unsigned*)maskv)[lane];
        bool gt1 = w0 > 1u;
        bool bad = ((w0 & 0xFFu) > 1u) | (((w0 >> 8) & 0xFFu) > 1u) |
                   (((w0 >> 16) & 0xFFu) > 1u) | ((w0 >> 24) > 1u);
        unsigned bg = __ballot_sync(0xFFFFFFFFu, gt1);
        unsigned bb = __ballot_sync(0xFFFFFFFFu, bad);
        mode = (bg == 0) ? 0 : (bb ? 2 : 1);
    }

    // ---- masks for my two cells ----
    const int c0 = cellBase + lane;
    const int c1 = cellBase + 32 + lane;
    bool m0 = false, m1 = false;
    if (mode == 0) {
        const int* mi = (const int*)maskv;
        if (c0 < ncell) m0 = mi[c0] != 0;
        if (c1 < ncell) m1 = mi[c1] != 0;
    } else if (mode == 1) {
        const unsigned char* mb = (const unsigned char*)maskv;
        if (c0 < ncell) m0 = mb[c0] != 0;
        if (c1 < ncell) m1 = mb[c1] != 0;
    } else {
        const float* mf = (const float*)maskv;
        if (c0 < ncell) m0 = mf[c0] != 0.0f;
        if (c1 < ncell) m1 = mf[c1] != 0.0f;
    }
    // 64-bit mask bitmap for the warp's tile
    unsigned mlo = __ballot_sync(0xFFFFFFFFu, m0);
    unsigned mhi = __ballot_sync(0xFFFFFFFFu, m1);
    const unsigned long long wmask = (unsigned long long)mlo |
                                     ((unsigned long long)mhi << 32);

    // ---- warp-autonomous pred staging via predicated cp.async ----
    // 64 cells = 1920 floats = 480 x 16B chunks. Chunk needed iff it
    // overlaps a masked cell, or contains pos 4 / pos 9 of its first cell.
    if (cellBase + CPW <= ncell) {
        const float4* gp4 = (const float4*)pred + (size_t)cellBase * 30 / 4;
        unsigned s4 = (unsigned)__cvta_generic_to_shared(wsp) + lane * 16u;
#pragma unroll
        for (int k = 0; k < 15; k++) {
            int i = lane + 32 * k;
            int f = 4 * i;                       // float offset in tile
            int cc1 = f / 30;
            int pos = f - cc1 * 30;              // 0..28 (even)
            int cc2 = (f + 3) / 30;
            bool conf = ((unsigned)(pos - 1) <= 3u) ||
                        ((unsigned)(pos - 6) <= 3u);
            bool need = conf || ((wmask >> cc1) & 1ull) ||
                        ((wmask >> cc2) & 1ull);
            if (need)
                asm volatile("cp.async.cg.shared.global [%0], [%1], 16;\n"
                             :: "r"(s4 + k * 32u * 16u),
                                "l"(gp4 + i));
        }
        asm volatile("cp.async.commit_group;\n");
        asm volatile("cp.async.wait_group 0;\n" ::: "memory");
    } else {
        // tail fallback (not taken when ncell is a multiple of CPB)
        const float* gp = pred + (size_t)cellBase * 30;
        long long lim = ((long long)ncell - cellBase) * 30;
        for (int f = lane; f < CPW * PROW; f += 32)
            if (f < lim) wsp[f] = gp[f];
    }
    __syncwarp();

    float s_cls = 0.f, s_noobj = 0.f, s_reg = 0.f, s_cont = 0.f;

    // ---- process my two cells ----
#pragma unroll
    for (int half = 0; half < 2; half++) {
        const int c = half ? c1 : c0;
        const bool m = half ? m1 : m0;
        if (c >= ncell) continue;

        const int r = lane + 32 * half;
        const float2* mp2 = (const float2*)(wsp + r * PROW);  // 8B-aligned

        if (!m) {
            float cf0 = mp2[2].x;   // float idx 4
            float cf1 = mp2[4].y;   // float idx 9
            s_noobj += cf0 * cf0 + cf1 * cf1;
        } else {
            float pv[10];
#pragma unroll
            for (int j = 0; j < 5; j++) {
                float2 v = mp2[j];
                pv[2 * j]     = v.x;
                pv[2 * j + 1] = v.y;
            }

            // ---- class loss: tcls streamed direct, pred classes from smem ----
            {
                const float4* tc4 = (const float4*)tcls + (size_t)c * 5;
                const float2* mc2 = (const float2*)(wsp + r * PROW + 10);
                float cls = 0.f;
#pragma unroll
                for (int j = 0; j < 5; j++) {
                    float4 t = __ldcs(tc4 + j);
                    float2 a = mc2[2 * j];
                    float2 b = mc2[2 * j + 1];
                    float d0 = t.x - a.x;
                    float d1 = t.y - a.y;
                    float d2 = t.z - b.x;
                    float d3 = t.w - b.y;
                    cls += d0 * d0 + d1 * d1 + d2 * d2 + d3 * d3;
                }
                s_cls += cls;
            }

            // ---- IoU of the two pred boxes vs target ----
            float4 tb = __ldcs(((const float4*)tbox) + c);
            float t_cx = tb.x * S_GRID_INV;
            float t_cy = tb.y * S_GRID_INV;
            float t_x1 = t_cx - 0.5f * tb.z;
            float t_y1 = t_cy - 0.5f * tb.w;
            float t_x2 = t_cx + 0.5f * tb.z;
            float t_y2 = t_cy + 0.5f * tb.w;
            float area_t = (t_x2 - t_x1) * (t_y2 - t_y1);

            float iou[2];
#pragma unroll
            for (int b = 0; b < 2; b++) {
                float px = pv[5 * b + 0] * S_GRID_INV;
                float py = pv[5 * b + 1] * S_GRID_INV;
                float pw = pv[5 * b + 2];
                float ph = pv[5 * b + 3];
                float p_x1 = px - 0.5f * pw;
                float p_y1 = py - 0.5f * ph;
                float p_x2 = px + 0.5f * pw;
                float p_y2 = py + 0.5f * ph;
                float lt_x = fmaxf(t_x1, p_x1);
                float lt_y = fmaxf(t_y1, p_y1);
                float rb_x = fminf(t_x2, p_x2);
                float rb_y = fminf(t_y2, p_y2);
                float w = fmaxf(rb_x - lt_x, 0.0f);
                float h = fmaxf(rb_y - lt_y, 0.0f);
                float inter = w * h;
                float area_p = (p_x2 - p_x1) * (p_y2 - p_y1);
                iou[b] = inter / (area_t + area_p - inter);
            }

            bool sel = iou[1] > iou[0];   // first max wins on tie
            float best_iou = sel ? iou[1] : iou[0];
            float bb_x = sel ? pv[5] : pv[0];
            float bb_y = sel ? pv[6] : pv[1];
            float bb_w = sel ? pv[7] : pv[2];
            float bb_h = sel ? pv[8] : pv[3];
            float bb_c = sel ? pv[9] : pv[4];

            float dx = bb_x - tb.x;
            float dy = bb_y - tb.y;
            float sw = sqrtf(bb_w) - sqrtf(tb.z);
            float sh = sqrtf(bb_h) - sqrtf(tb.w);
            s_reg += dx * dx + dy * dy + sw * sw + sh * sh;

            float dc = best_iou - bb_c;
            s_cont += dc * dc;
        }
    }

    // ---- warp reduction, then block reduction ----
#pragma unroll
    for (int off = 16; off; off >>= 1) {
        s_cls   += __shfl_down_sync(0xFFFFFFFFu, s_cls,   off);
        s_noobj += __shfl_down_sync(0xFFFFFFFFu, s_noobj, off);
        s_reg   += __shfl_down_sync(0xFFFFFFFFu, s_reg,   off);
        s_cont  += __shfl_down_sync(0xFFFFFFFFu, s_cont,  off);
    }
    if (lane == 0) {
        sm[0][warp] = s_cls;
        sm[1][warp] = s_noobj;
        sm[2][warp] = s_reg;
        sm[3][warp] = s_cont;
    }
    __syncthreads();

    if (tid == 0) {
        float a0 = 0.f, a1 = 0.f, a2 = 0.f, a3 = 0.f;
#pragma unroll
        for (int w = 0; w < NWARP; w++) {
            a0 += sm[0][w];
            a1 += sm[1][w];
            a2 += sm[2][w];
            a3 += sm[3][w];
        }
        atomicAdd(&g_acc[0], (double)a0);
        atomicAdd(&g_acc[1], (double)a1);
        atomicAdd(&g_acc[2], (double)a2);
        atomicAdd(&g_acc[3], (double)a3);

        __threadfence();
        unsigned old = atomicAdd(&g_counter, 1u);
        s_last = (old == gridDim.x - 1);
    }
    __syncthreads();

    // ---- last block: finalize + reset persistent state ----
    if (s_last && tid == 0) {
        double cls   = atomicAdd(&g_acc[0], 0.0);
        double noobj = (double)L_NOOBJ * atomicAdd(&g_acc[1], 0.0);
        double reg   = (double)L_COORD * atomicAdd(&g_acc[2], 0.0);
        double cont  = atomicAdd(&g_acc[3], 0.0);
        double total = (cls + noobj + reg + cont) / (double)n_batch;
        out[0] = (float)total;
        out[1] = (float)reg;
        out[2] = (float)cont;
        out[3] = (float)noobj;
        out[4] = (float)cls;
        g_acc[0] = 0.0; g_acc[1] = 0.0; g_acc[2] = 0.0; g_acc[3] = 0.0;
        __threadfence();
        g_counter = 0u;
    }
}

extern "C" void kernel_launch(void* const* d_in, const int* in_sizes, int n_in,
                              void* d_out, int out_size) {
    // Identify inputs by element count: pred = 30n, tcls = 20n, tbox = 4n, mask = n
    const void* ptrs[4] = {d_in[0], d_in[1], d_in[2], d_in[3]};
    long long sz[4] = {in_sizes[0], in_sizes[1], in_sizes[2], in_sizes[3]};

    int im = 0;
    for (int i = 1; i < 4; i++) if (sz[i] < sz[im]) im = i;
    long long n = sz[im];

    const float* pred = nullptr;
    const float* tbox = nullptr;
    const float* tcls = nullptr;
    const void*  hmask = ptrs[im];
    for (int i = 0; i < 4; i++) {
        if (i == im) continue;
        if (sz[i] == 30 * n) pred = (const float*)ptrs[i];
        else if (sz[i] == 20 * n) tcls = (const float*)ptrs[i];
        else if (sz[i] == 4 * n) tbox = (const float*)ptrs[i];
    }

    int ncell = (int)n;                 // 802816
    int n_batch = ncell / (14 * 14);    // 4096

    int blocks = (ncell + CPB - 1) / CPB;  // 3136
    yolo_fused_kernel<<<blocks, TPB>>>(pred, tbox, tcls, hmask,
                                       ncell, n_batch, (float*)d_out);
}

// round 13
// speedup vs baseline: 1.4869x; 1.4113x over previous
#include <cuda_runtime.h>
#include <math.h>

// YOLO loss — fused single launch. Warp-level double-buffered cp.async
// pipeline: each warp grid-strides over 32-cell tiles, staging tile t+1
// while computing tile t. tcls/tbox streamed direct. Outputs 5 f32.

#define S_GRID_INV (1.0f / 14.0f)
#define L_COORD 5.0f
#define L_NOOBJ 0.5f
#define TPB 128
#define NWARP (TPB / 32)
#define CPW 32                   // cells per warp-tile
#define TILE_FL (CPW * 30)       // 960 floats = 3840 B
#define TILE_CH (CPW * 120 / 16) // 240 x 16B chunks

__device__ double g_acc[4];      // cls, noobj(raw), reg(raw), containing
__device__ unsigned g_counter;   // zero-init; reset by last block each run

__device__ __forceinline__ bool loadMask(const void* maskv, int mode,
                                         int c, int ncell) {
    if (c >= ncell) return false;
    if (mode == 0)  return ((const int*)maskv)[c] != 0;
    if (mode == 1)  return ((const unsigned char*)maskv)[c] != 0;
    return ((const float*)maskv)[c] != 0.0f;
}

__device__ __forceinline__ void stageTile(const float* __restrict__ pred,
                                          int cellBase, int lane, int ncell,
                                          unsigned sbuf) {
    const char* gp = (const char*)(pred + (size_t)cellBase * 30);
    long long bytes = ((long long)ncell - cellBase) * 120;
#pragma unroll
    for (int k = 0; k < 8; k++) {
        int ch = lane + 32 * k;
        long long off = (long long)ch * 16;
        if (ch < TILE_CH && off < bytes)
            asm volatile("cp.async.cg.shared.global [%0], [%1], 16;\n"
                         :: "r"(sbuf + (unsigned)(ch * 16)), "l"(gp + off));
    }
    asm volatile("cp.async.commit_group;\n");
}

__device__ __forceinline__ void computeTile(
    const float* buf, int cellBase, int lane, int ncell, bool m,
    const float* __restrict__ tbox, const float* __restrict__ tcls,
    float& s_cls, float& s_noobj, float& s_reg, float& s_cont)
{
    const int c = cellBase + lane;
    if (c >= ncell) return;

    const float2* mp2 = (const float2*)(buf + lane * 30);   // 8B aligned

    if (!m) {
        float cf0 = mp2[2].x;    // pred float idx 4
        float cf1 = mp2[4].y;    // pred float idx 9
        s_noobj += cf0 * cf0 + cf1 * cf1;
        return;
    }

    float pv[10];
#pragma unroll
    for (int j = 0; j < 5; j++) {
        float2 v = mp2[j];
        pv[2 * j]     = v.x;
        pv[2 * j + 1] = v.y;
    }

    // ---- class loss: tcls streamed direct, pred classes from smem ----
    {
        const float4* tc4 = (const float4*)tcls + (size_t)c * 5;
        const float2* mc2 = (const float2*)(buf + lane * 30 + 10);
        float cls = 0.f;
#pragma unroll
        for (int j = 0; j < 5; j++) {
            float4 t = __ldcs(tc4 + j);
            float2 a = mc2[2 * j];
            float2 b = mc2[2 * j + 1];
            float d0 = t.x - a.x;
            float d1 = t.y - a.y;
            float d2 = t.z - b.x;
            float d3 = t.w - b.y;
            cls += d0 * d0 + d1 * d1 + d2 * d2 + d3 * d3;
        }
        s_cls += cls;
    }

    // ---- IoU of the two pred boxes vs target ----
    float4 tb = __ldcs(((const float4*)tbox) + c);
    float t_cx = tb.x * S_GRID_INV;
    float t_cy = tb.y * S_GRID_INV;
    float t_x1 = t_cx - 0.5f * tb.z;
    float t_y1 = t_cy - 0.5f * tb.w;
    float t_x2 = t_cx + 0.5f * tb.z;
    float t_y2 = t_cy + 0.5f * tb.w;
    float area_t = (t_x2 - t_x1) * (t_y2 - t_y1);

    float iou[2];
#pragma unroll
    for (int b = 0; b < 2; b++) {
        float px = pv[5 * b + 0] * S_GRID_INV;
        float py = pv[5 * b + 1] * S_GRID_INV;
        float pw = pv[5 * b + 2];
        float ph = pv[5 * b + 3];
        float p_x1 = px - 0.5f * pw;
        float p_y1 = py - 0.5f * ph;
        float p_x2 = px + 0.5f * pw;
        float p_y2 = py + 0.5f * ph;
        float lt_x = fmaxf(t_x1, p_x1);
        float lt_y = fmaxf(t_y1, p_y1);
        float rb_x = fminf(t_x2, p_x2);
        float rb_y = fminf(t_y2, p_y2);
        float w = fmaxf(rb_x - lt_x, 0.0f);
        float h = fmaxf(rb_y - lt_y, 0.0f);
        float inter = w * h;
        float area_p = (p_x2 - p_x1) * (p_y2 - p_y1);
        iou[b] = inter / (area_t + area_p - inter);
    }

    bool sel = iou[1] > iou[0];    // first max wins on tie
    float best_iou = sel ? iou[1] : iou[0];
    float bb_x = sel ? pv[5] : pv[0];
    float bb_y = sel ? pv[6] : pv[1];
    float bb_w = sel ? pv[7] : pv[2];
    float bb_h = sel ? pv[8] : pv[3];
    float bb_c = sel ? pv[9] : pv[4];

    float dx = bb_x - tb.x;
    float dy = bb_y - tb.y;
    float sw = sqrtf(bb_w) - sqrtf(tb.z);
    float sh = sqrtf(bb_h) - sqrtf(tb.w);
    s_reg += dx * dx + dy * dy + sw * sw + sh * sh;

    float dc = best_iou - bb_c;
    s_cont += dc * dc;
}

__global__ void __launch_bounds__(TPB, 7) yolo_fused_kernel(
    const float* __restrict__ pred,
    const float* __restrict__ tbox,
    const float* __restrict__ tcls,
    const void* __restrict__ maskv,
    int ncell, int n_batch, int ntiles, float* __restrict__ out)
{
    __shared__ float sp[NWARP][2][TILE_FL];   // 30.7 KB
    __shared__ float sm[4][NWARP];
    __shared__ bool s_last;

    const int tid  = threadIdx.x;
    const int warp = tid >> 5;
    const int lane = tid & 31;
    const int gw = blockIdx.x * NWARP + warp;        // global warp id
    const int wstride = gridDim.x * NWARP;

    unsigned sb[2];
    sb[0] = (unsigned)__cvta_generic_to_shared(&sp[warp][0][0]);
    sb[1] = (unsigned)__cvta_generic_to_shared(&sp[warp][1][0]);

    // ---- mask dtype detection: warp-local ballot over first 32 words ----
    int mode;
    {
        unsigned w0 = ((const unsigned*)maskv)[lane];
        bool gt1 = w0 > 1u;
        bool bad = ((w0 & 0xFFu) > 1u) | (((w0 >> 8) & 0xFFu) > 1u) |
                   (((w0 >> 16) & 0xFFu) > 1u) | ((w0 >> 24) > 1u);
        unsigned bg = __ballot_sync(0xFFFFFFFFu, gt1);
        unsigned bb = __ballot_sync(0xFFFFFFFFu, bad);
        mode = (bg == 0) ? 0 : (bb ? 2 : 1);
    }

    float s_cls = 0.f, s_noobj = 0.f, s_reg = 0.f, s_cont = 0.f;

    // ---- warp-level double-buffered pipeline over grid-strided tiles ----
    int t = gw;
    if (t < ntiles) {
        stageTile(pred, t * CPW, lane, ncell, sb[0]);
        bool mCur = loadMask(maskv, mode, t * CPW + lane, ncell);

        int tn = t + wstride;
        int sel = 0;
        while (true) {
            bool hasN = tn < ntiles;
            bool mNext = false;
            if (hasN) {
                stageTile(pred, tn * CPW, lane, ncell, sb[sel ^ 1]);
                mNext = loadMask(maskv, mode, tn * CPW + lane, ncell);
            }
            if (hasN) { asm volatile("cp.async.wait_group 1;\n" ::: "memory"); }
            else      { asm volatile("cp.async.wait_group 0;\n" ::: "memory"); }
            __syncwarp();

            computeTile(&sp[warp][sel][0], t * CPW, lane, ncell, mCur,
                        tbox, tcls, s_cls, s_noobj, s_reg, s_cont);

            if (!hasN) break;
            t = tn; tn += wstride; mCur = mNext; sel ^= 1;
            __syncwarp();   // all lanes done with old buffer before restage
        }
    }

    // ---- warp reduction, then block reduction ----
#pragma unroll
    for (int off = 16; off; off >>= 1) {
        s_cls   += __shfl_down_sync(0xFFFFFFFFu, s_cls,   off);
        s_noobj += __shfl_down_sync(0xFFFFFFFFu, s_noobj, off);
        s_reg   += __shfl_down_sync(0xFFFFFFFFu, s_reg,   off);
        s_cont  += __shfl_down_sync(0xFFFFFFFFu, s_cont,  off);
    }
    if (lane == 0) {
        sm[0][warp] = s_cls;
        sm[1][warp] = s_noobj;
        sm[2][warp] = s_reg;
        sm[3][warp] = s_cont;
    }
    __syncthreads();

    if (tid == 0) {
        float a0 = 0.f, a1 = 0.f, a2 = 0.f, a3 = 0.f;
#pragma unroll
        for (int w = 0; w < NWARP; w++) {
            a0 += sm[0][w];
            a1 += sm[1][w];
            a2 += sm[2][w];
            a3 += sm[3][w];
        }
        atomicAdd(&g_acc[0], (double)a0);
        atomicAdd(&g_acc[1], (double)a1);
        atomicAdd(&g_acc[2], (double)a2);
        atomicAdd(&g_acc[3], (double)a3);

        __threadfence();
        unsigned old = atomicAdd(&g_counter, 1u);
        s_last = (old == gridDim.x - 1);
    }
    __syncthreads();

    // ---- last block: finalize + reset persistent state ----
    if (s_last && tid == 0) {
        double cls   = atomicAdd(&g_acc[0], 0.0);
        double noobj = (double)L_NOOBJ * atomicAdd(&g_acc[1], 0.0);
        double reg   = (double)L_COORD * atomicAdd(&g_acc[2], 0.0);
        double cont  = atomicAdd(&g_acc[3], 0.0);
        double total = (cls + noobj + reg + cont) / (double)n_batch;
        out[0] = (float)total;
        out[1] = (float)reg;
        out[2] = (float)cont;
        out[3] = (float)noobj;
        out[4] = (float)cls;
        g_acc[0] = 0.0; g_acc[1] = 0.0; g_acc[2] = 0.0; g_acc[3] = 0.0;
        __threadfence();
        g_counter = 0u;
    }
}

extern "C" void kernel_launch(void* const* d_in, const int* in_sizes, int n_in,
                              void* d_out, int out_size) {
    // Identify inputs by element count: pred = 30n, tcls = 20n, tbox = 4n, mask = n
    const void* ptrs[4] = {d_in[0], d_in[1], d_in[2], d_in[3]};
    long long sz[4] = {in_sizes[0], in_sizes[1], in_sizes[2], in_sizes[3]};

    int im = 0;
    for (int i = 1; i < 4; i++) if (sz[i] < sz[im]) im = i;
    long long n = sz[im];

    const float* pred = nullptr;
    const float* tbox = nullptr;
    const float* tcls = nullptr;
    const void*  hmask = ptrs[im];
    for (int i = 0; i < 4; i++) {
        if (i == im) continue;
        if (sz[i] == 30 * n) pred = (const float*)ptrs[i];
        else if (sz[i] == 20 * n) tcls = (const float*)ptrs[i];
        else if (sz[i] == 4 * n) tbox = (const float*)ptrs[i];
    }

    int ncell = (int)n;                   // 802816
    int n_batch = ncell / (14 * 14);      // 4096
    int ntiles = (ncell + CPW - 1) / CPW; // 25088

    int dev = 0, nsm = 148;
    cudaGetDevice(&dev);
    cudaDeviceGetAttribute(&nsm, cudaDevAttrMultiProcessorCount, dev);

    int blocks = nsm * 7;                 // 7 blocks/SM, grid-strided tiles
    int maxBlocks = (ntiles + NWARP - 1) / NWARP;
    if (blocks > maxBlocks) blocks = maxBlocks;

    yolo_fused_kernel<<<blocks, TPB>>>(pred, tbox, tcls, hmask,
                                       ncell, n_batch, ntiles, (float*)d_out);
}